// round 3
// baseline (speedup 1.0000x reference)
#include <cuda_runtime.h>
#include <cuda_bf16.h>
#include <math_constants.h>

// ---------------- problem constants ----------------
#define NEDGE   65536
#define NATOMS  2048
#define NRAD    24
#define NCOMP   5            // 1 two-body + 4 zeta components
#define NELEM   94
#define NEMB    16
#define NK      69           // total (lx,ly,lz) monomials across zeta=1..4
#define NSLOT   (NRAD*NK + NRAD)   // 1680 accumulation slots
#define NFEAT   216          // 24 * (1 + 2*4)
#define H1DIM   256
#define H2DIM   128

// ---------------- angular tables (zeta = 1,2,3,4) ----------------
__constant__ int   c_LX[NK] = {
  0,0,0,1,
  0,0,0,1, 0,0,0,1,1,2,
  0,0,0,1, 0,0,0,1,1,2, 0,0,0,0,1,1,1,2,2,3,
  0,0,0,1, 0,0,0,1,1,2, 0,0,0,0,1,1,1,2,2,3, 0,0,0,0,0,1,1,1,1,2,2,2,3,3,4 };
__constant__ int   c_LY[NK] = {
  0,0,1,0,
  0,0,1,0, 0,1,2,0,1,0,
  0,0,1,0, 0,1,2,0,1,0, 0,1,2,3,0,1,2,0,1,0,
  0,0,1,0, 0,1,2,0,1,0, 0,1,2,3,0,1,2,0,1,0, 0,1,2,3,4,0,1,2,3,0,1,2,0,1,0 };
__constant__ int   c_LZ[NK] = {
  0,1,0,0,
  0,1,0,0, 2,1,0,1,0,0,
  0,1,0,0, 2,1,0,1,0,0, 3,2,1,0,2,1,0,1,0,0,
  0,1,0,0, 2,1,0,1,0,0, 3,2,1,0,2,1,0,1,0,0, 4,3,2,1,0,3,2,1,0,2,1,0,1,0,0 };
__constant__ float c_FNORM[NK] = {
  1,1,1,1,
  1,2,2,2, 1,2,1,2,2,1,
  1,3,3,3, 3,6,3,6,6,3, 1,3,3,1,3,6,3,3,3,1,
  1,4,4,4, 6,12,6,12,12,6, 4,12,12,4,12,24,12,12,12,4,
  1,4,6,4,1, 4,12,12,4, 6,12,6, 4,4, 1 };
__constant__ float c_LAM[NK] = {
  1,-1,-1,-1,
  1,-1,-1,-1, 1,1,1,1,1,1,
  1,-1,-1,-1, 1,1,1,1,1,1, -1,-1,-1,-1,-1,-1,-1,-1,-1,-1,
  1,-1,-1,-1, 1,1,1,1,1,1, -1,-1,-1,-1,-1,-1,-1,-1,-1,-1,
  1,1,1,1,1, 1,1,1,1, 1,1,1, 1,1, 1 };
__constant__ int   c_KOFF[5] = {0, 4, 14, 34, 69};
__constant__ float c_NORMZ[4] = {1.0f, 0.5f, 0.25f, 0.125f};  // 2^{1-z}

// ---------------- scratch (static device globals; no runtime alloc) ----------------
__device__ float g_radial[NEDGE * NRAD * NCOMP];          // [E,120]
__device__ float g_feat[NATOMS * NFEAT];                  // [nat,216]
__device__ float g_embS[NELEM * NEMB];                    // per-species embedding
__device__ float g_Wt[NELEM * NFEAT * H1DIM];             // 94*216*256 precontracted
__device__ float g_h1[NATOMS * H1DIM];
__device__ float g_ebuf[NATOMS];
__device__ int   g_offs[NELEM + 1];
__device__ int   g_order[NATOMS];

__device__ __forceinline__ float silu_f(float v) {
    return __fdividef(v, 1.0f + __expf(-v));
}

// ================= Kernel 1: per-edge radial MLP (24 -> 64 -> 120) =================
__global__ void __launch_bounds__(256)
k_radial(const float* __restrict__ rij,
         const float* __restrict__ Wr1, const float* __restrict__ br1,
         const float* __restrict__ Wr2, const float* __restrict__ br2)
{
    __shared__ float sW1[NRAD * 64];
    __shared__ float sB1[64];
    __shared__ float sW2[64 * 120];
    __shared__ float sB2[120];
    int tid = threadIdx.x;
    for (int i = tid; i < NRAD * 64; i += 256) sW1[i] = Wr1[i];
    for (int i = tid; i < 64; i += 256)        sB1[i] = br1[i];
    for (int i = tid; i < 64 * 120; i += 256)  sW2[i] = Wr2[i];
    for (int i = tid; i < 120; i += 256)       sB2[i] = br2[i];
    __syncthreads();

    int e = blockIdx.x * 256 + tid;
    if (e >= NEDGE) return;

    float x = rij[e * 3 + 0], y = rij[e * 3 + 1], z = rij[e * 3 + 2];
    float r  = sqrtf(x * x + y * y + z * z);
    float rc = fminf(r, 6.0f);
    float fc = 0.5f * (__cosf(rc * (float)(CUDART_PI / 6.0)) + 1.0f);

    float h[64];
    #pragma unroll
    for (int j = 0; j < 64; j++) h[j] = sB1[j];

    for (int i = 0; i < NRAD; i++) {           // basis computed on the fly
        float d = r - (6.0f / 23.0f) * (float)i;
        float b = __expf(-8.0f * d * d) * fc;  // 1/(2*w^2) = 8, w = 0.25
        const float4* w4 = reinterpret_cast<const float4*>(sW1 + i * 64);
        #pragma unroll
        for (int q = 0; q < 16; q++) {
            float4 w = w4[q];
            h[q*4+0] += b * w.x; h[q*4+1] += b * w.y;
            h[q*4+2] += b * w.z; h[q*4+3] += b * w.w;
        }
    }
    #pragma unroll
    for (int j = 0; j < 64; j++) h[j] = silu_f(h[j]);

    // second layer in 5 chunks of 24 outputs
    for (int c = 0; c < 120; c += 24) {
        float o[24];
        #pragma unroll
        for (int j = 0; j < 24; j++) o[j] = sB2[c + j];
        #pragma unroll
        for (int i = 0; i < 64; i++) {
            float hv = h[i];
            const float4* w4 = reinterpret_cast<const float4*>(sW2 + i * 120 + c);
            #pragma unroll
            for (int q = 0; q < 6; q++) {
                float4 w = w4[q];
                o[q*4+0] += hv * w.x; o[q*4+1] += hv * w.y;
                o[q*4+2] += hv * w.z; o[q*4+3] += hv * w.w;
            }
        }
        #pragma unroll
        for (int j = 0; j < 24; j++)
            g_radial[e * 120 + c + j] = silu_f(o[j]);
    }
}

// ---------------- binary search (first_atom_idx is sorted) ----------------
__device__ __forceinline__ int lower_bound_i(const int* __restrict__ a, int n, int v) {
    int lo = 0, hi = n;
    while (lo < hi) { int mid = (lo + hi) >> 1; if (a[mid] < v) lo = mid + 1; else hi = mid; }
    return lo;
}

// ================= Kernel 2: per-atom angular accumulation + features =================
__global__ void __launch_bounds__(256)
k_accum(const float* __restrict__ rij, const int* __restrict__ fai)
{
    __shared__ float s_rad[120];
    __shared__ float s_gij[NK + 1];
    __shared__ float s_acc[NSLOT];
    __shared__ int   s_range[2];

    int a = blockIdx.x;
    int tid = threadIdx.x;
    if (tid == 0) {
        s_range[0] = lower_bound_i(fai, NEDGE, a);
        s_range[1] = lower_bound_i(fai, NEDGE, a + 1);
        s_gij[NK] = 1.0f;   // sentinel for two-body slots
    }
    __syncthreads();
    int lo = s_range[0], hi = s_range[1];

    // per-thread slot assignment (<=7 slots each)
    float acc[7];
    int   aidx[7], kidx[7], ns = 0;
    for (int s = tid; s < NSLOT; s += 256) {
        if (s < NRAD * NK) {
            int rad = s / NK, k = s % NK;
            int iz = (k < 4) ? 0 : (k < 14) ? 1 : (k < 34) ? 2 : 3;
            aidx[ns] = rad * NCOMP + (iz + 1);
            kidx[ns] = k;
        } else {
            int rad = s - NRAD * NK;
            aidx[ns] = rad * NCOMP;      // comp 0 (two-body)
            kidx[ns] = NK;
        }
        acc[ns] = 0.0f;
        ns++;
    }

    for (int e = lo; e < hi; e++) {
        if (tid < 120) s_rad[tid] = g_radial[e * 120 + tid];
        if (tid < NK) {
            float x = rij[e * 3 + 0], y = rij[e * 3 + 1], z = rij[e * 3 + 2];
            float inv = rsqrtf(x * x + y * y + z * z);
            float ux = x * inv + 1e-12f, uy = y * inv + 1e-12f, uz = z * inv + 1e-12f;
            int lx = c_LX[tid], ly = c_LY[tid], lz = c_LZ[tid];
            float g = c_FNORM[tid];
            #pragma unroll
            for (int i = 0; i < 4; i++) if (i < lx) g *= ux;
            #pragma unroll
            for (int i = 0; i < 4; i++) if (i < ly) g *= uy;
            #pragma unroll
            for (int i = 0; i < 4; i++) if (i < lz) g *= uz;
            s_gij[tid] = g;
        }
        __syncthreads();
        #pragma unroll
        for (int i = 0; i < 7; i++)
            if (i < ns) acc[i] += s_rad[aidx[i]] * s_gij[kidx[i]];
        __syncthreads();
    }

    { int i = 0; for (int s = tid; s < NSLOT; s += 256) s_acc[s] = acc[i++]; }
    __syncthreads();

    if (tid < NFEAT) {
        float v;
        if (tid < NRAD) {
            v = s_acc[NRAD * NK + tid];                       // two-body
        } else {
            int t = tid - NRAD;
            int iz = t / 48, sgn = (t % 48) / 24, rad = t % 24;
            int k0 = c_KOFF[iz], k1 = c_KOFF[iz + 1];
            float s = 0.0f;
            for (int k = k0; k < k1; k++) {
                float g = s_acc[rad * NK + k];
                float g2 = g * g;
                s += sgn ? g2 * c_LAM[k] : g2;
            }
            v = s * c_NORMZ[iz];
        }
        g_feat[a * NFEAT + tid] = v;
    }
}

// ================= Kernel 3: per-species embedding (94 species) =================
__global__ void k_emb(const float* __restrict__ Ws1, const float* __restrict__ bs1,
                      const float* __restrict__ Ws2, const float* __restrict__ bs2)
{
    __shared__ float t1[32];
    int s = blockIdx.x, tid = threadIdx.x;
    t1[tid] = silu_f(Ws1[s * 32 + tid] + bs1[tid]);
    __syncwarp();
    if (tid < NEMB) {
        float acc = bs2[tid];
        #pragma unroll
        for (int j = 0; j < 32; j++) acc += t1[j] * Ws2[j * NEMB + tid];
        g_embS[s * NEMB + tid] = acc;
    }
}

// ================= Kernel 4: group atoms by species (deterministic) =================
__global__ void k_group(const int* __restrict__ species)
{
    __shared__ int cnt[NELEM];
    __shared__ int offs[NELEM + 1];
    int tid = threadIdx.x;
    for (int i = tid; i < NELEM; i += 128) cnt[i] = 0;
    __syncthreads();
    for (int a = tid; a < NATOMS; a += 128) atomicAdd(&cnt[species[a]], 1);
    __syncthreads();
    if (tid == 0) {
        offs[0] = 0;
        for (int s = 0; s < NELEM; s++) offs[s + 1] = offs[s] + cnt[s];
        for (int s = 0; s <= NELEM; s++) g_offs[s] = offs[s];
    }
    __syncthreads();
    if (tid < NELEM) {                 // deterministic stable scatter
        int p = offs[tid];
        for (int a = 0; a < NATOMS; a++)
            if (species[a] == tid) g_order[p++] = a;
    }
}

// ================= Kernel 5: Wtilde[s,f,n] = sum_j embS[s,j] * Wa1[16f+j, n] =================
__global__ void __launch_bounds__(256)
k_wtilde(const float* __restrict__ Wa1)
{
    __shared__ float s_emb[NELEM * NEMB];
    int f = blockIdx.x, n = threadIdx.x;
    for (int i = threadIdx.x; i < NELEM * NEMB; i += 256) s_emb[i] = g_embS[i];
    float w[NEMB];
    #pragma unroll
    for (int j = 0; j < NEMB; j++) w[j] = Wa1[(f * NEMB + j) * H1DIM + n];
    __syncthreads();
    for (int s = 0; s < NELEM; s++) {
        float acc = 0.0f;
        #pragma unroll
        for (int j = 0; j < NEMB; j++) acc += s_emb[s * NEMB + j] * w[j];
        g_Wt[(s * NFEAT + f) * H1DIM + n] = acc;
    }
}

// ================= Kernel 6: h1 = silu(feat @ Wtilde[species] + ba1), species-grouped =================
__global__ void __launch_bounds__(128)
k_gemm1(const float* __restrict__ ba1)
{
    __shared__ float shf[NFEAT * 16];          // [f][a] transposed, float4-friendly
    int s = blockIdx.x;
    int n = blockIdx.y * 128 + threadIdx.x;
    int tid = threadIdx.x;
    int base = g_offs[s];
    int cnt  = g_offs[s + 1] - base;

    for (int chunk = blockIdx.z * 16; chunk < cnt; chunk += 32) {
        int m = min(16, cnt - chunk);
        for (int idx = tid; idx < NFEAT * 16; idx += 128) {
            int aq = idx / NFEAT, f = idx - aq * NFEAT;
            float v = 0.0f;
            if (aq < m) {
                int atom = g_order[base + chunk + aq];
                v = g_feat[atom * NFEAT + f];
            }
            shf[f * 16 + aq] = v;
        }
        __syncthreads();

        float acc[16];
        float b = ba1[n];
        #pragma unroll
        for (int q = 0; q < 16; q++) acc[q] = b;

        const float* wp = g_Wt + (s * NFEAT) * H1DIM + n;
        for (int f = 0; f < NFEAT; f++) {
            float w = wp[f * H1DIM];
            const float4* s4 = reinterpret_cast<const float4*>(shf + f * 16);
            #pragma unroll
            for (int q = 0; q < 4; q++) {
                float4 fv = s4[q];
                acc[q*4+0] += fv.x * w; acc[q*4+1] += fv.y * w;
                acc[q*4+2] += fv.z * w; acc[q*4+3] += fv.w * w;
            }
        }
        for (int aq = 0; aq < m; aq++) {
            int atom = g_order[base + chunk + aq];
            g_h1[atom * H1DIM + n] = silu_f(acc[aq]);
        }
        __syncthreads();
    }
}

// ================= Kernel 7: tail MLP 256->128->1 per atom (16 atoms/block) =================
__global__ void __launch_bounds__(128)
k_tail(const float* __restrict__ Wa2, const float* __restrict__ ba2,
       const float* __restrict__ Wa3, const float* __restrict__ ba3)
{
    __shared__ float sh[H1DIM * 16];   // [k][a]
    __shared__ float she[16 * 128];
    int a0 = blockIdx.x * 16;
    int tid = threadIdx.x;
    for (int idx = tid; idx < H1DIM * 16; idx += 128) {
        int aq = idx / H1DIM, k = idx - aq * H1DIM;
        sh[k * 16 + aq] = g_h1[(a0 + aq) * H1DIM + k];
    }
    __syncthreads();

    float acc[16];
    float b = ba2[tid];
    #pragma unroll
    for (int q = 0; q < 16; q++) acc[q] = b;
    for (int k = 0; k < H1DIM; k++) {
        float w = Wa2[k * H2DIM + tid];
        const float4* s4 = reinterpret_cast<const float4*>(sh + k * 16);
        #pragma unroll
        for (int q = 0; q < 4; q++) {
            float4 hv = s4[q];
            acc[q*4+0] += hv.x * w; acc[q*4+1] += hv.y * w;
            acc[q*4+2] += hv.z * w; acc[q*4+3] += hv.w * w;
        }
    }
    float w3 = Wa3[tid];
    #pragma unroll
    for (int aq = 0; aq < 16; aq++) she[aq * 128 + tid] = silu_f(acc[aq]) * w3;
    __syncthreads();
    if (tid < 16) {
        float s = ba3[0];
        for (int m = 0; m < 128; m++) s += she[tid * 128 + m];
        g_ebuf[a0 + tid] = s;
    }
}

// ================= Kernel 8: deterministic tree reduction =================
__global__ void k_reduce(float* __restrict__ out)
{
    __shared__ float sr[1024];
    int tid = threadIdx.x;
    sr[tid] = g_ebuf[tid] + g_ebuf[tid + 1024];
    __syncthreads();
    for (int s = 512; s > 0; s >>= 1) {
        if (tid < s) sr[tid] += sr[tid + s];
        __syncthreads();
    }
    if (tid == 0) out[0] = sr[0];
}

// ================= launch =================
extern "C" void kernel_launch(void* const* d_in, const int* in_sizes, int n_in,
                              void* d_out, int out_size)
{
    const float* rij  = (const float*)d_in[0];
    const float* Wr1  = (const float*)d_in[1];
    const float* br1  = (const float*)d_in[2];
    const float* Wr2  = (const float*)d_in[3];
    const float* br2  = (const float*)d_in[4];
    const float* Ws1  = (const float*)d_in[5];
    const float* bs1  = (const float*)d_in[6];
    const float* Ws2  = (const float*)d_in[7];
    const float* bs2  = (const float*)d_in[8];
    const float* Wa1  = (const float*)d_in[9];
    const float* ba1  = (const float*)d_in[10];
    const float* ba2  = (const float*)d_in[12];
    const float* Wa2  = (const float*)d_in[11];
    const float* Wa3  = (const float*)d_in[13];
    const float* ba3  = (const float*)d_in[14];
    const int*   fai  = (const int*)d_in[15];
    const int*   spc  = (const int*)d_in[16];
    float* out = (float*)d_out;

    k_radial<<<NEDGE / 256, 256>>>(rij, Wr1, br1, Wr2, br2);
    k_emb<<<NELEM, 32>>>(Ws1, bs1, Ws2, bs2);
    k_group<<<1, 128>>>(spc);
    k_wtilde<<<NFEAT, 256>>>(Wa1);
    k_accum<<<NATOMS, 256>>>(rij, fai);
    k_gemm1<<<dim3(NELEM, 2, 2), 128>>>(ba1);
    k_tail<<<NATOMS / 16, 128>>>(Wa2, ba2, Wa3, ba3);
    k_reduce<<<1, 1024>>>(out);
}

// round 4
// speedup vs baseline: 1.1268x; 1.1268x over previous
#include <cuda_runtime.h>
#include <cuda_bf16.h>
#include <math_constants.h>

// ---------------- problem constants ----------------
#define NEDGE   65536
#define NATOMS  2048
#define NRAD    24
#define NCOMP   5            // 1 two-body + 4 zeta components
#define NELEM   94
#define NEMB    16
#define NK      69           // total (lx,ly,lz) monomials across zeta=1..4
#define NSLOT   (NRAD*NK + NRAD)   // 1680 accumulation slots
#define NFEAT   216          // 24 * (1 + 2*4)
#define H1DIM   256
#define H2DIM   128

// ---------------- angular tables (zeta = 1,2,3,4) ----------------
__constant__ int   c_LX[NK] = {
  0,0,0,1,
  0,0,0,1, 0,0,0,1,1,2,
  0,0,0,1, 0,0,0,1,1,2, 0,0,0,0,1,1,1,2,2,3,
  0,0,0,1, 0,0,0,1,1,2, 0,0,0,0,1,1,1,2,2,3, 0,0,0,0,0,1,1,1,1,2,2,2,3,3,4 };
__constant__ int   c_LY[NK] = {
  0,0,1,0,
  0,0,1,0, 0,1,2,0,1,0,
  0,0,1,0, 0,1,2,0,1,0, 0,1,2,3,0,1,2,0,1,0,
  0,0,1,0, 0,1,2,0,1,0, 0,1,2,3,0,1,2,0,1,0, 0,1,2,3,4,0,1,2,3,0,1,2,0,1,0 };
__constant__ int   c_LZ[NK] = {
  0,1,0,0,
  0,1,0,0, 2,1,0,1,0,0,
  0,1,0,0, 2,1,0,1,0,0, 3,2,1,0,2,1,0,1,0,0,
  0,1,0,0, 2,1,0,1,0,0, 3,2,1,0,2,1,0,1,0,0, 4,3,2,1,0,3,2,1,0,2,1,0,1,0,0 };
__constant__ float c_FNORM[NK] = {
  1,1,1,1,
  1,2,2,2, 1,2,1,2,2,1,
  1,3,3,3, 3,6,3,6,6,3, 1,3,3,1,3,6,3,3,3,1,
  1,4,4,4, 6,12,6,12,12,6, 4,12,12,4,12,24,12,12,12,4,
  1,4,6,4,1, 4,12,12,4, 6,12,6, 4,4, 1 };
__constant__ float c_LAM[NK] = {
  1,-1,-1,-1,
  1,-1,-1,-1, 1,1,1,1,1,1,
  1,-1,-1,-1, 1,1,1,1,1,1, -1,-1,-1,-1,-1,-1,-1,-1,-1,-1,
  1,-1,-1,-1, 1,1,1,1,1,1, -1,-1,-1,-1,-1,-1,-1,-1,-1,-1,
  1,1,1,1,1, 1,1,1,1, 1,1,1, 1,1, 1 };
__constant__ int   c_KOFF[5] = {0, 4, 14, 34, 69};
__constant__ float c_NORMZ[4] = {1.0f, 0.5f, 0.25f, 0.125f};  // 2^{1-z}

// ---------------- scratch (static device globals; no runtime alloc) ----------------
__device__ float g_radial[NEDGE * NRAD * NCOMP];          // [E,120]
__device__ float g_feat[NATOMS * NFEAT];                  // [nat,216]
__device__ float g_embS[NELEM * NEMB];                    // per-species embedding
__device__ float g_Wt[NELEM * NFEAT * H1DIM];             // 94*216*256 precontracted
__device__ float g_h1[NATOMS * H1DIM];
__device__ float g_ebuf[NATOMS];
__device__ int   g_offs[NELEM + 1];
__device__ int   g_order[NATOMS];

__device__ __forceinline__ float silu_f(float v) {
    return __fdividef(v, 1.0f + __expf(-v));
}

// ---------------- packed f32x2 helpers (sm_103a FFMA2) ----------------
typedef unsigned long long u64t;
__device__ __forceinline__ u64t pk2(float lo, float hi) {
    u64t r; asm("mov.b64 %0, {%1,%2};" : "=l"(r) : "f"(lo), "f"(hi)); return r;
}
__device__ __forceinline__ void upk2(float& lo, float& hi, u64t v) {
    asm("mov.b64 {%0,%1}, %2;" : "=f"(lo), "=f"(hi) : "l"(v));
}
__device__ __forceinline__ void fma2(u64t& d, u64t a, u64t b) {
    asm("fma.rn.f32x2 %0, %1, %2, %3;" : "=l"(d) : "l"(a), "l"(b), "l"(d));
}

// ================= Kernel 1: per-edge radial MLP (24 -> 64 -> 120), f32x2 =================
__global__ void __launch_bounds__(256)
k_radial(const float* __restrict__ rij,
         const float* __restrict__ Wr1, const float* __restrict__ br1,
         const float* __restrict__ Wr2, const float* __restrict__ br2)
{
    __shared__ __align__(16) float sW1[NRAD * 64];
    __shared__ __align__(16) float sB1[64];
    __shared__ __align__(16) float sW2[64 * 120];
    __shared__ __align__(16) float sB2[120];
    int tid = threadIdx.x;
    for (int i = tid; i < NRAD * 64; i += 256) sW1[i] = Wr1[i];
    for (int i = tid; i < 64; i += 256)        sB1[i] = br1[i];
    for (int i = tid; i < 64 * 120; i += 256)  sW2[i] = Wr2[i];
    for (int i = tid; i < 120; i += 256)       sB2[i] = br2[i];
    __syncthreads();

    int e = blockIdx.x * 256 + tid;
    if (e >= NEDGE) return;

    float x = rij[e * 3 + 0], y = rij[e * 3 + 1], z = rij[e * 3 + 2];
    float r  = sqrtf(x * x + y * y + z * z);
    float rc = fminf(r, 6.0f);
    float fc = 0.5f * (__cosf(rc * (float)(CUDART_PI / 6.0)) + 1.0f);

    // layer 1: 24 -> 64 with packed FFMA2
    u64t h2[32];
    {
        const u64t* b2 = reinterpret_cast<const u64t*>(sB1);
        #pragma unroll
        for (int q = 0; q < 32; q++) h2[q] = b2[q];
    }
    for (int i = 0; i < NRAD; i++) {
        float d = r - (6.0f / 23.0f) * (float)i;
        float b = __expf(-8.0f * d * d) * fc;  // 1/(2*w^2) = 8, w = 0.25
        u64t bb = pk2(b, b);
        const u64t* w2 = reinterpret_cast<const u64t*>(sW1 + i * 64);
        #pragma unroll
        for (int q = 0; q < 32; q++) fma2(h2[q], bb, w2[q]);
    }
    float h[64];
    #pragma unroll
    for (int q = 0; q < 32; q++) {
        float a, b; upk2(a, b, h2[q]);
        h[2*q+0] = silu_f(a); h[2*q+1] = silu_f(b);
    }

    // layer 2: 64 -> 120 in chunks of 24 outputs (12 packed accumulators)
    for (int c = 0; c < 120; c += 24) {
        u64t o2[12];
        {
            const u64t* b2 = reinterpret_cast<const u64t*>(sB2 + c);
            #pragma unroll
            for (int j = 0; j < 12; j++) o2[j] = b2[j];
        }
        #pragma unroll
        for (int i = 0; i < 64; i++) {
            u64t hh = pk2(h[i], h[i]);
            const u64t* w2 = reinterpret_cast<const u64t*>(sW2 + i * 120 + c);
            #pragma unroll
            for (int j = 0; j < 12; j++) fma2(o2[j], hh, w2[j]);
        }
        #pragma unroll
        for (int j = 0; j < 12; j++) {
            float a, b; upk2(a, b, o2[j]);
            g_radial[e * 120 + c + 2*j + 0] = silu_f(a);
            g_radial[e * 120 + c + 2*j + 1] = silu_f(b);
        }
    }
}

// ---------------- binary search (first_atom_idx is sorted) ----------------
__device__ __forceinline__ int lower_bound_i(const int* __restrict__ a, int n, int v) {
    int lo = 0, hi = n;
    while (lo < hi) { int mid = (lo + hi) >> 1; if (a[mid] < v) lo = mid + 1; else hi = mid; }
    return lo;
}

// ================= Kernel 2: per-atom angular accumulation + features =================
// Processes 2 edges per barrier pair to halve sync count and exposed latency.
__global__ void __launch_bounds__(256)
k_accum(const float* __restrict__ rij, const int* __restrict__ fai)
{
    __shared__ float s_rad[2][120];
    __shared__ float s_gij[2][NK + 1];
    __shared__ float s_acc[NSLOT];
    __shared__ int   s_range[2];

    int a = blockIdx.x;
    int tid = threadIdx.x;
    if (tid == 0) {
        s_range[0] = lower_bound_i(fai, NEDGE, a);
        s_range[1] = lower_bound_i(fai, NEDGE, a + 1);
        s_gij[0][NK] = 1.0f;   // sentinel for two-body slots
        s_gij[1][NK] = 1.0f;
    }
    __syncthreads();
    int lo = s_range[0], hi = s_range[1];

    // per-thread slot assignment (<=7 slots each)
    float acc[7];
    int   aidx[7], kidx[7], ns = 0;
    for (int s = tid; s < NSLOT; s += 256) {
        if (s < NRAD * NK) {
            int rad = s / NK, k = s % NK;
            int iz = (k < 4) ? 0 : (k < 14) ? 1 : (k < 34) ? 2 : 3;
            aidx[ns] = rad * NCOMP + (iz + 1);
            kidx[ns] = k;
        } else {
            int rad = s - NRAD * NK;
            aidx[ns] = rad * NCOMP;      // comp 0 (two-body)
            kidx[ns] = NK;
        }
        acc[ns] = 0.0f;
        ns++;
    }

    for (int e = lo; e < hi; e += 2) {
        if (tid < 240) {
            int which = (tid >= 120);
            int idx = tid - which * 120;
            int ee = e + which;
            s_rad[which][idx] = (ee < hi) ? g_radial[ee * 120 + idx] : 0.0f;
        }
        if (tid < 138) {
            int which = (tid >= NK);
            int k = tid - which * NK;
            int ee = e + which;
            float g = 0.0f;
            if (ee < hi) {
                float x = rij[ee * 3 + 0], y = rij[ee * 3 + 1], z = rij[ee * 3 + 2];
                float inv = rsqrtf(x * x + y * y + z * z);
                float ux = x * inv + 1e-12f, uy = y * inv + 1e-12f, uz = z * inv + 1e-12f;
                int lx = c_LX[k], ly = c_LY[k], lz = c_LZ[k];
                g = c_FNORM[k];
                #pragma unroll
                for (int i = 0; i < 4; i++) if (i < lx) g *= ux;
                #pragma unroll
                for (int i = 0; i < 4; i++) if (i < ly) g *= uy;
                #pragma unroll
                for (int i = 0; i < 4; i++) if (i < lz) g *= uz;
            }
            s_gij[which][k] = g;
        }
        __syncthreads();
        #pragma unroll
        for (int i = 0; i < 7; i++)
            if (i < ns)
                acc[i] += s_rad[0][aidx[i]] * s_gij[0][kidx[i]]
                        + s_rad[1][aidx[i]] * s_gij[1][kidx[i]];
        __syncthreads();
    }

    { int i = 0; for (int s = tid; s < NSLOT; s += 256) s_acc[s] = acc[i++]; }
    __syncthreads();

    if (tid < NFEAT) {
        float v;
        if (tid < NRAD) {
            v = s_acc[NRAD * NK + tid];                       // two-body
        } else {
            int t = tid - NRAD;
            int iz = t / 48, sgn = (t % 48) / 24, rad = t % 24;
            int k0 = c_KOFF[iz], k1 = c_KOFF[iz + 1];
            float s = 0.0f;
            for (int k = k0; k < k1; k++) {
                float g = s_acc[rad * NK + k];
                float g2 = g * g;
                s += sgn ? g2 * c_LAM[k] : g2;
            }
            v = s * c_NORMZ[iz];
        }
        g_feat[a * NFEAT + tid] = v;
    }
}

// ================= Kernel 3: per-species embedding (94 species) =================
__global__ void k_emb(const float* __restrict__ Ws1, const float* __restrict__ bs1,
                      const float* __restrict__ Ws2, const float* __restrict__ bs2)
{
    __shared__ float t1[32];
    int s = blockIdx.x, tid = threadIdx.x;
    t1[tid] = silu_f(Ws1[s * 32 + tid] + bs1[tid]);
    __syncwarp();
    if (tid < NEMB) {
        float acc = bs2[tid];
        #pragma unroll
        for (int j = 0; j < 32; j++) acc += t1[j] * Ws2[j * NEMB + tid];
        g_embS[s * NEMB + tid] = acc;
    }
}

// ================= Kernel 4: group atoms by species (parallel atomic rank) ===========
// Order within a species is value-irrelevant: each atom's downstream outputs depend
// only on its own feat row, so any within-species permutation produces bit-identical
// results. This lets us use atomic ranking instead of a serial stable scan.
__global__ void __launch_bounds__(256)
k_group(const int* __restrict__ species)
{
    __shared__ int cnt[NELEM];
    __shared__ int offs[NELEM + 1];
    __shared__ int cursor[NELEM];
    int tid = threadIdx.x;
    for (int i = tid; i < NELEM; i += 256) cnt[i] = 0;
    __syncthreads();
    for (int a = tid; a < NATOMS; a += 256) atomicAdd(&cnt[species[a]], 1);
    __syncthreads();
    if (tid == 0) {
        int run = 0;
        for (int s = 0; s < NELEM; s++) { offs[s] = run; run += cnt[s]; }
        offs[NELEM] = run;
    }
    __syncthreads();
    for (int i = tid; i <= NELEM; i += 256) g_offs[i] = offs[i];
    for (int i = tid; i < NELEM; i += 256) cursor[i] = offs[i];
    __syncthreads();
    for (int a = tid; a < NATOMS; a += 256) {
        int p = atomicAdd(&cursor[species[a]], 1);
        g_order[p] = a;
    }
}

// ================= Kernel 5: Wtilde[s,f,n] = sum_j embS[s,j] * Wa1[16f+j, n] =========
// grid (NFEAT, 6): each block handles 16 species for one f, 1296 blocks total.
__global__ void __launch_bounds__(256)
k_wtilde(const float* __restrict__ Wa1)
{
    __shared__ float s_emb[16 * NEMB];
    int f = blockIdx.x, n = threadIdx.x;
    int s0 = blockIdx.y * 16;
    if (threadIdx.x < 16 * NEMB) {
        int s = s0 + threadIdx.x / NEMB;
        s_emb[threadIdx.x] = (s < NELEM) ? g_embS[s * NEMB + (threadIdx.x % NEMB)] : 0.0f;
    }
    float w[NEMB];
    #pragma unroll
    for (int j = 0; j < NEMB; j++) w[j] = Wa1[(f * NEMB + j) * H1DIM + n];
    __syncthreads();
    #pragma unroll 4
    for (int ss = 0; ss < 16; ss++) {
        int s = s0 + ss;
        if (s >= NELEM) break;
        float acc = 0.0f;
        #pragma unroll
        for (int j = 0; j < NEMB; j++) acc += s_emb[ss * NEMB + j] * w[j];
        g_Wt[(s * NFEAT + f) * H1DIM + n] = acc;
    }
}

// ================= Kernel 6: h1 = silu(feat @ Wtilde[species] + ba1), species-grouped =
__global__ void __launch_bounds__(128)
k_gemm1(const float* __restrict__ ba1)
{
    __shared__ float shf[NFEAT * 16];          // [f][a] transposed, float4-friendly
    int s = blockIdx.x;
    int n = blockIdx.y * 128 + threadIdx.x;
    int tid = threadIdx.x;
    int base = g_offs[s];
    int cnt  = g_offs[s + 1] - base;

    for (int chunk = blockIdx.z * 16; chunk < cnt; chunk += 32) {
        int m = min(16, cnt - chunk);
        for (int idx = tid; idx < NFEAT * 16; idx += 128) {
            int aq = idx / NFEAT, f = idx - aq * NFEAT;
            float v = 0.0f;
            if (aq < m) {
                int atom = g_order[base + chunk + aq];
                v = g_feat[atom * NFEAT + f];
            }
            shf[f * 16 + aq] = v;
        }
        __syncthreads();

        float acc[16];
        float b = ba1[n];
        #pragma unroll
        for (int q = 0; q < 16; q++) acc[q] = b;

        const float* wp = g_Wt + (s * NFEAT) * H1DIM + n;
        for (int f = 0; f < NFEAT; f++) {
            float w = wp[f * H1DIM];
            const float4* s4 = reinterpret_cast<const float4*>(shf + f * 16);
            #pragma unroll
            for (int q = 0; q < 4; q++) {
                float4 fv = s4[q];
                acc[q*4+0] += fv.x * w; acc[q*4+1] += fv.y * w;
                acc[q*4+2] += fv.z * w; acc[q*4+3] += fv.w * w;
            }
        }
        for (int aq = 0; aq < m; aq++) {
            int atom = g_order[base + chunk + aq];
            g_h1[atom * H1DIM + n] = silu_f(acc[aq]);
        }
        __syncthreads();
    }
}

// ================= Kernel 7: tail MLP 256->128->1 per atom (16 atoms/block) ==========
__global__ void __launch_bounds__(128)
k_tail(const float* __restrict__ Wa2, const float* __restrict__ ba2,
       const float* __restrict__ Wa3, const float* __restrict__ ba3)
{
    __shared__ float sh[H1DIM * 16];   // [k][a]
    __shared__ float she[16 * 128];
    int a0 = blockIdx.x * 16;
    int tid = threadIdx.x;
    for (int idx = tid; idx < H1DIM * 16; idx += 128) {
        int aq = idx / H1DIM, k = idx - aq * H1DIM;
        sh[k * 16 + aq] = g_h1[(a0 + aq) * H1DIM + k];
    }
    __syncthreads();

    float acc[16];
    float b = ba2[tid];
    #pragma unroll
    for (int q = 0; q < 16; q++) acc[q] = b;
    for (int k = 0; k < H1DIM; k++) {
        float w = Wa2[k * H2DIM + tid];
        const float4* s4 = reinterpret_cast<const float4*>(sh + k * 16);
        #pragma unroll
        for (int q = 0; q < 4; q++) {
            float4 hv = s4[q];
            acc[q*4+0] += hv.x * w; acc[q*4+1] += hv.y * w;
            acc[q*4+2] += hv.z * w; acc[q*4+3] += hv.w * w;
        }
    }
    float w3 = Wa3[tid];
    #pragma unroll
    for (int aq = 0; aq < 16; aq++) she[aq * 128 + tid] = silu_f(acc[aq]) * w3;
    __syncthreads();
    if (tid < 16) {
        float s = ba3[0];
        for (int m = 0; m < 128; m++) s += she[tid * 128 + m];
        g_ebuf[a0 + tid] = s;
    }
}

// ================= Kernel 8: deterministic tree reduction =================
__global__ void k_reduce(float* __restrict__ out)
{
    __shared__ float sr[1024];
    int tid = threadIdx.x;
    sr[tid] = g_ebuf[tid] + g_ebuf[tid + 1024];
    __syncthreads();
    for (int s = 512; s > 0; s >>= 1) {
        if (tid < s) sr[tid] += sr[tid + s];
        __syncthreads();
    }
    if (tid == 0) out[0] = sr[0];
}

// ================= launch =================
extern "C" void kernel_launch(void* const* d_in, const int* in_sizes, int n_in,
                              void* d_out, int out_size)
{
    const float* rij  = (const float*)d_in[0];
    const float* Wr1  = (const float*)d_in[1];
    const float* br1  = (const float*)d_in[2];
    const float* Wr2  = (const float*)d_in[3];
    const float* br2  = (const float*)d_in[4];
    const float* Ws1  = (const float*)d_in[5];
    const float* bs1  = (const float*)d_in[6];
    const float* Ws2  = (const float*)d_in[7];
    const float* bs2  = (const float*)d_in[8];
    const float* Wa1  = (const float*)d_in[9];
    const float* ba1  = (const float*)d_in[10];
    const float* Wa2  = (const float*)d_in[11];
    const float* ba2  = (const float*)d_in[12];
    const float* Wa3  = (const float*)d_in[13];
    const float* ba3  = (const float*)d_in[14];
    const int*   fai  = (const int*)d_in[15];
    const int*   spc  = (const int*)d_in[16];
    float* out = (float*)d_out;

    k_radial<<<NEDGE / 256, 256>>>(rij, Wr1, br1, Wr2, br2);
    k_emb<<<NELEM, 32>>>(Ws1, bs1, Ws2, bs2);
    k_group<<<1, 256>>>(spc);
    k_wtilde<<<dim3(NFEAT, 6), 256>>>(Wa1);
    k_accum<<<NATOMS, 256>>>(rij, fai);
    k_gemm1<<<dim3(NELEM, 2, 2), 128>>>(ba1);
    k_tail<<<NATOMS / 16, 128>>>(Wa2, ba2, Wa3, ba3);
    k_reduce<<<1, 1024>>>(out);
}

// round 7
// speedup vs baseline: 1.1720x; 1.0401x over previous
#include <cuda_runtime.h>
#include <cuda_bf16.h>
#include <math_constants.h>

// ---------------- problem constants ----------------
#define NEDGE   65536
#define NATOMS  2048
#define NRAD    24
#define NCOMP   5            // 1 two-body + 4 zeta components
#define NELEM   94
#define NEMB    16
#define NK      69           // total (lx,ly,lz) monomials across zeta=1..4
#define NSLOT   (NRAD*NK + NRAD)   // 1680 accumulation slots
#define NFEAT   216          // 24 * (1 + 2*4)
#define H1DIM   256
#define H2DIM   128
#define EB      4            // edges per accumulation batch

// ---------------- angular tables (zeta = 1,2,3,4) ----------------
__constant__ int   c_LX[NK] = {
  0,0,0,1,
  0,0,0,1, 0,0,0,1,1,2,
  0,0,0,1, 0,0,0,1,1,2, 0,0,0,0,1,1,1,2,2,3,
  0,0,0,1, 0,0,0,1,1,2, 0,0,0,0,1,1,1,2,2,3, 0,0,0,0,0,1,1,1,1,2,2,2,3,3,4 };
__constant__ int   c_LY[NK] = {
  0,0,1,0,
  0,0,1,0, 0,1,2,0,1,0,
  0,0,1,0, 0,1,2,0,1,0, 0,1,2,3,0,1,2,0,1,0,
  0,0,1,0, 0,1,2,0,1,0, 0,1,2,3,0,1,2,0,1,0, 0,1,2,3,4,0,1,2,3,0,1,2,0,1,0 };
__constant__ int   c_LZ[NK] = {
  0,1,0,0,
  0,1,0,0, 2,1,0,1,0,0,
  0,1,0,0, 2,1,0,1,0,0, 3,2,1,0,2,1,0,1,0,0,
  0,1,0,0, 2,1,0,1,0,0, 3,2,1,0,2,1,0,1,0,0, 4,3,2,1,0,3,2,1,0,2,1,0,1,0,0 };
__constant__ float c_FNORM[NK] = {
  1,1,1,1,
  1,2,2,2, 1,2,1,2,2,1,
  1,3,3,3, 3,6,3,6,6,3, 1,3,3,1,3,6,3,3,3,1,
  1,4,4,4, 6,12,6,12,12,6, 4,12,12,4,12,24,12,12,12,4,
  1,4,6,4,1, 4,12,12,4, 6,12,6, 4,4, 1 };
__constant__ float c_LAM[NK] = {
  1,-1,-1,-1,
  1,-1,-1,-1, 1,1,1,1,1,1,
  1,-1,-1,-1, 1,1,1,1,1,1, -1,-1,-1,-1,-1,-1,-1,-1,-1,-1,
  1,-1,-1,-1, 1,1,1,1,1,1, -1,-1,-1,-1,-1,-1,-1,-1,-1,-1,
  1,1,1,1,1, 1,1,1,1, 1,1,1, 1,1, 1 };
__constant__ int   c_KOFF[5] = {0, 4, 14, 34, 69};
__constant__ float c_NORMZ[4] = {1.0f, 0.5f, 0.25f, 0.125f};  // 2^{1-z}

// ---------------- scratch (static device globals; no runtime alloc) ----------------
__device__ float g_radial[NEDGE * NRAD * NCOMP];          // [E,120]
__device__ float g_feat[NATOMS * NFEAT];                  // [nat,216]
__device__ float g_embS[NELEM * NEMB];                    // per-species embedding
__device__ float g_Wt[NELEM * NFEAT * H1DIM];             // 94*216*256 precontracted
__device__ float g_h1[NATOMS * H1DIM];
__device__ float g_ebuf[NATOMS];
__device__ int   g_offs[NELEM + 1];
__device__ int   g_order[NATOMS];

__device__ __forceinline__ float silu_f(float v) {
    return __fdividef(v, 1.0f + __expf(-v));
}

// ---------------- packed f32x2 helpers (sm_103a FFMA2) ----------------
typedef unsigned long long u64t;
__device__ __forceinline__ u64t pk2(float lo, float hi) {
    u64t r; asm("mov.b64 %0, {%1,%2};" : "=l"(r) : "f"(lo), "f"(hi)); return r;
}
__device__ __forceinline__ void upk2(float& lo, float& hi, u64t v) {
    asm("mov.b64 {%0,%1}, %2;" : "=f"(lo), "=f"(hi) : "l"(v));
}
__device__ __forceinline__ void fma2(u64t& d, u64t a, u64t b) {
    asm("fma.rn.f32x2 %0, %1, %2, %3;" : "=l"(d) : "l"(a), "l"(b), "l"(d));
}

// ================= Kernel 1: per-edge radial MLP (24 -> 64 -> 120), f32x2 =================
__global__ void __launch_bounds__(256)
k_radial(const float* __restrict__ rij,
         const float* __restrict__ Wr1, const float* __restrict__ br1,
         const float* __restrict__ Wr2, const float* __restrict__ br2)
{
    __shared__ __align__(16) float sW1[NRAD * 64];
    __shared__ __align__(16) float sB1[64];
    __shared__ __align__(16) float sW2[64 * 120];
    __shared__ __align__(16) float sB2[120];
    int tid = threadIdx.x;
    for (int i = tid; i < NRAD * 64; i += 256) sW1[i] = Wr1[i];
    for (int i = tid; i < 64; i += 256)        sB1[i] = br1[i];
    for (int i = tid; i < 64 * 120; i += 256)  sW2[i] = Wr2[i];
    for (int i = tid; i < 120; i += 256)       sB2[i] = br2[i];
    __syncthreads();

    int e = blockIdx.x * 256 + tid;
    if (e >= NEDGE) return;

    float x = rij[e * 3 + 0], y = rij[e * 3 + 1], z = rij[e * 3 + 2];
    float r  = sqrtf(x * x + y * y + z * z);
    float rc = fminf(r, 6.0f);
    float fc = 0.5f * (__cosf(rc * (float)(CUDART_PI / 6.0)) + 1.0f);

    // layer 1: 24 -> 64 with packed FFMA2
    u64t h2[32];
    {
        const u64t* b2 = reinterpret_cast<const u64t*>(sB1);
        #pragma unroll
        for (int q = 0; q < 32; q++) h2[q] = b2[q];
    }
    for (int i = 0; i < NRAD; i++) {
        float d = r - (6.0f / 23.0f) * (float)i;
        float b = __expf(-8.0f * d * d) * fc;  // 1/(2*w^2) = 8, w = 0.25
        u64t bb = pk2(b, b);
        const u64t* w2 = reinterpret_cast<const u64t*>(sW1 + i * 64);
        #pragma unroll
        for (int q = 0; q < 32; q++) fma2(h2[q], bb, w2[q]);
    }
    float h[64];
    #pragma unroll
    for (int q = 0; q < 32; q++) {
        float a, b; upk2(a, b, h2[q]);
        h[2*q+0] = silu_f(a); h[2*q+1] = silu_f(b);
    }

    // layer 2: 64 -> 120 in chunks of 24 outputs (12 packed accumulators)
    for (int c = 0; c < 120; c += 24) {
        u64t o2[12];
        {
            const u64t* b2 = reinterpret_cast<const u64t*>(sB2 + c);
            #pragma unroll
            for (int j = 0; j < 12; j++) o2[j] = b2[j];
        }
        #pragma unroll
        for (int i = 0; i < 64; i++) {
            u64t hh = pk2(h[i], h[i]);
            const u64t* w2 = reinterpret_cast<const u64t*>(sW2 + i * 120 + c);
            #pragma unroll
            for (int j = 0; j < 12; j++) fma2(o2[j], hh, w2[j]);
        }
        #pragma unroll
        for (int j = 0; j < 12; j++) {
            float a, b; upk2(a, b, o2[j]);
            g_radial[e * 120 + c + 2*j + 0] = silu_f(a);
            g_radial[e * 120 + c + 2*j + 1] = silu_f(b);
        }
    }
}

// ---------------- binary search (first_atom_idx is sorted) ----------------
__device__ __forceinline__ int lower_bound_i(const int* __restrict__ a, int n, int v) {
    int lo = 0, hi = n;
    while (lo < hi) { int mid = (lo + hi) >> 1; if (a[mid] < v) lo = mid + 1; else hi = mid; }
    return lo;
}

// ================= Kernel 2: per-atom angular accumulation + features =================
// 4 edges per batch, double-buffered shared staging, ONE barrier per batch.
__global__ void __launch_bounds__(256)
k_accum(const float* __restrict__ rij, const int* __restrict__ fai)
{
    __shared__ __align__(16) float s_rad[2][EB * 120];   // 4 contiguous radial rows
    __shared__ float s_gij[2][EB * (NK + 1)];            // 70 per edge; [69] = validity sentinel
    __shared__ float s_acc[NSLOT];
    __shared__ int   s_range[2];

    int a = blockIdx.x;
    int tid = threadIdx.x;
    if (tid == 0) {
        s_range[0] = lower_bound_i(fai, NEDGE, a);
        s_range[1] = lower_bound_i(fai, NEDGE, a + 1);
    }
    __syncthreads();
    int lo = s_range[0], hi = s_range[1];

    // per-thread slot assignment (<=7 slots each)
    float acc[7];
    int   aidx[7], kidx[7], ns = 0;
    for (int s = tid; s < NSLOT; s += 256) {
        if (s < NRAD * NK) {
            int rad = s / NK, k = s % NK;
            int iz = (k < 4) ? 0 : (k < 14) ? 1 : (k < 34) ? 2 : 3;
            aidx[ns] = rad * NCOMP + (iz + 1);
            kidx[ns] = k;
        } else {
            int rad = s - NRAD * NK;
            aidx[ns] = rad * NCOMP;      // comp 0 (two-body)
            kidx[ns] = NK;               // sentinel column
        }
        acc[ns] = 0.0f;
        ns++;
    }

    int nb = (hi - lo + EB - 1) / EB;

    // ---- batch loader: 4 edges -> buffer `buf` ----
    #define LOAD_BATCH(E0, BUF)                                                  \
    do {                                                                         \
        int e0_ = (E0);                                                          \
        if (tid < EB * 30) {      /* 120 float4 = 4 contiguous 120-float rows */ \
            int eedge = e0_ + tid / 30;                                          \
            float4 v = make_float4(0.f, 0.f, 0.f, 0.f);                          \
            if (eedge < NEDGE)                                                   \
                v = reinterpret_cast<const float4*>(g_radial)[e0_ * 30 + tid];   \
            reinterpret_cast<float4*>(s_rad[BUF])[tid] = v;                      \
        }                                                                        \
        for (int t = tid; t < EB * (NK + 1); t += 256) {                         \
            int w = t / (NK + 1), k = t - w * (NK + 1);                          \
            int ee = e0_ + w;                                                    \
            float g = 0.0f;                                                      \
            if (ee < hi) {                                                       \
                if (k == NK) g = 1.0f;                                           \
                else {                                                           \
                    float x = rij[ee * 3 + 0], y = rij[ee * 3 + 1], z = rij[ee * 3 + 2]; \
                    float inv = rsqrtf(x * x + y * y + z * z);                   \
                    float ux = x * inv + 1e-12f, uy = y * inv + 1e-12f, uz = z * inv + 1e-12f; \
                    int lx = c_LX[k], ly = c_LY[k], lz = c_LZ[k];                \
                    g = c_FNORM[k];                                              \
                    _Pragma("unroll")                                            \
                    for (int i = 0; i < 4; i++) if (i < lx) g *= ux;             \
                    _Pragma("unroll")                                            \
                    for (int i = 0; i < 4; i++) if (i < ly) g *= uy;             \
                    _Pragma("unroll")                                            \
                    for (int i = 0; i < 4; i++) if (i < lz) g *= uz;             \
                }                                                                \
            }                                                                    \
            s_gij[BUF][t] = g;                                                   \
        }                                                                        \
    } while (0)

    if (nb > 0) LOAD_BATCH(lo, 0);
    __syncthreads();

    for (int t = 0; t < nb; t++) {
        int p = t & 1;
        if (t + 1 < nb) LOAD_BATCH(lo + (t + 1) * EB, p ^ 1);
        #pragma unroll
        for (int i = 0; i < 7; i++) {
            if (i < ns) {
                float sum = 0.0f;
                #pragma unroll
                for (int w = 0; w < EB; w++)
                    sum += s_rad[p][w * 120 + aidx[i]] * s_gij[p][w * (NK + 1) + kidx[i]];
                acc[i] += sum;
            }
        }
        __syncthreads();
    }
    #undef LOAD_BATCH

    { int i = 0; for (int s = tid; s < NSLOT; s += 256) s_acc[s] = acc[i++]; }
    __syncthreads();

    if (tid < NFEAT) {
        float v;
        if (tid < NRAD) {
            v = s_acc[NRAD * NK + tid];                       // two-body
        } else {
            int t = tid - NRAD;
            int iz = t / 48, sgn = (t % 48) / 24, rad = t % 24;
            int k0 = c_KOFF[iz], k1 = c_KOFF[iz + 1];
            float s = 0.0f;
            for (int k = k0; k < k1; k++) {
                float g = s_acc[rad * NK + k];
                float g2 = g * g;
                s += sgn ? g2 * c_LAM[k] : g2;
            }
            v = s * c_NORMZ[iz];
        }
        g_feat[a * NFEAT + tid] = v;
    }
}

// ================= Kernel 3: per-species embedding (94 species) =================
__global__ void k_emb(const float* __restrict__ Ws1, const float* __restrict__ bs1,
                      const float* __restrict__ Ws2, const float* __restrict__ bs2)
{
    __shared__ float t1[32];
    int s = blockIdx.x, tid = threadIdx.x;
    t1[tid] = silu_f(Ws1[s * 32 + tid] + bs1[tid]);
    __syncwarp();
    if (tid < NEMB) {
        float acc = bs2[tid];
        #pragma unroll
        for (int j = 0; j < 32; j++) acc += t1[j] * Ws2[j * NEMB + tid];
        g_embS[s * NEMB + tid] = acc;
    }
}

// ================= Kernel 4: group atoms by species (parallel atomic rank) ===========
// Within-species order is value-irrelevant (per-atom outputs depend only on the
// atom's own feature row), so an unstable atomic rank is bit-exact downstream.
__global__ void __launch_bounds__(256)
k_group(const int* __restrict__ species)
{
    __shared__ int cnt[NELEM];
    __shared__ int offs[NELEM + 1];
    __shared__ int cursor[NELEM];
    int tid = threadIdx.x;
    for (int i = tid; i < NELEM; i += 256) cnt[i] = 0;
    __syncthreads();
    for (int a = tid; a < NATOMS; a += 256) atomicAdd(&cnt[species[a]], 1);
    __syncthreads();
    if (tid == 0) {
        int run = 0;
        for (int s = 0; s < NELEM; s++) { offs[s] = run; run += cnt[s]; }
        offs[NELEM] = run;
    }
    __syncthreads();
    for (int i = tid; i <= NELEM; i += 256) g_offs[i] = offs[i];
    for (int i = tid; i < NELEM; i += 256) cursor[i] = offs[i];
    __syncthreads();
    for (int a = tid; a < NATOMS; a += 256) {
        int p = atomicAdd(&cursor[species[a]], 1);
        g_order[p] = a;
    }
}

// ================= Kernel 5: Wtilde[s,f,n] = sum_j embS[s,j] * Wa1[16f+j, n] =========
// j-outer / species-inner: 16 independent accumulators -> ILP 16 (was a serial chain).
__global__ void __launch_bounds__(256)
k_wtilde(const float* __restrict__ Wa1)
{
    __shared__ float s_emb[16 * NEMB];
    int f = blockIdx.x, n = threadIdx.x;
    int s0 = blockIdx.y * 16;
    if (threadIdx.x < 16 * NEMB) {
        int s = s0 + threadIdx.x / NEMB;
        s_emb[threadIdx.x] = (s < NELEM) ? g_embS[s * NEMB + (threadIdx.x % NEMB)] : 0.0f;
    }
    float w[NEMB];
    #pragma unroll
    for (int j = 0; j < NEMB; j++) w[j] = Wa1[(f * NEMB + j) * H1DIM + n];
    __syncthreads();

    float acc[16];
    #pragma unroll
    for (int ss = 0; ss < 16; ss++) acc[ss] = 0.0f;
    #pragma unroll
    for (int j = 0; j < NEMB; j++) {
        float wj = w[j];
        #pragma unroll
        for (int ss = 0; ss < 16; ss++)
            acc[ss] += s_emb[ss * NEMB + j] * wj;
    }
    #pragma unroll
    for (int ss = 0; ss < 16; ss++) {
        int s = s0 + ss;
        if (s < NELEM)
            g_Wt[((size_t)s * NFEAT + f) * H1DIM + n] = acc[ss];
    }
}

// ================= Kernel 6: h1 = silu(feat @ Wtilde[species] + ba1), species-grouped =
// f-loop unrolled x8 with register prefetch of weights -> MLP 8 on g_Wt loads.
__global__ void __launch_bounds__(128)
k_gemm1(const float* __restrict__ ba1)
{
    __shared__ float shf[NFEAT * 16];          // [f][a] transposed, float4-friendly
    int s = blockIdx.x;
    int n = blockIdx.y * 128 + threadIdx.x;
    int tid = threadIdx.x;
    int base = g_offs[s];
    int cnt  = g_offs[s + 1] - base;

    for (int chunk = blockIdx.z * 16; chunk < cnt; chunk += 32) {
        int m = min(16, cnt - chunk);
        for (int idx = tid; idx < NFEAT * 16; idx += 128) {
            int aq = idx / NFEAT, f = idx - aq * NFEAT;
            float v = 0.0f;
            if (aq < m) {
                int atom = g_order[base + chunk + aq];
                v = g_feat[atom * NFEAT + f];
            }
            shf[f * 16 + aq] = v;
        }
        __syncthreads();

        float acc[16];
        float b = ba1[n];
        #pragma unroll
        for (int q = 0; q < 16; q++) acc[q] = b;

        const float* wp = g_Wt + (size_t)s * NFEAT * H1DIM + n;
        #pragma unroll 1
        for (int f0 = 0; f0 < NFEAT; f0 += 8) {      // 216 = 27 * 8
            float wr[8];
            #pragma unroll
            for (int u = 0; u < 8; u++) wr[u] = wp[(size_t)(f0 + u) * H1DIM];
            #pragma unroll
            for (int u = 0; u < 8; u++) {
                float w = wr[u];
                const float4* s4 = reinterpret_cast<const float4*>(shf + (f0 + u) * 16);
                float4 a0 = s4[0], a1 = s4[1], a2 = s4[2], a3 = s4[3];
                acc[ 0] += a0.x * w; acc[ 1] += a0.y * w; acc[ 2] += a0.z * w; acc[ 3] += a0.w * w;
                acc[ 4] += a1.x * w; acc[ 5] += a1.y * w; acc[ 6] += a1.z * w; acc[ 7] += a1.w * w;
                acc[ 8] += a2.x * w; acc[ 9] += a2.y * w; acc[10] += a2.z * w; acc[11] += a2.w * w;
                acc[12] += a3.x * w; acc[13] += a3.y * w; acc[14] += a3.z * w; acc[15] += a3.w * w;
            }
        }
        for (int aq = 0; aq < m; aq++) {
            int atom = g_order[base + chunk + aq];
            g_h1[atom * H1DIM + n] = silu_f(acc[aq]);
        }
        __syncthreads();
    }
}

// ================= Kernel 7: tail MLP 256->128->1 per atom (16 atoms/block) ==========
__global__ void __launch_bounds__(128)
k_tail(const float* __restrict__ Wa2, const float* __restrict__ ba2,
       const float* __restrict__ Wa3, const float* __restrict__ ba3)
{
    __shared__ float sh[H1DIM * 16];   // [k][a]
    __shared__ float she[16 * 128];
    int a0 = blockIdx.x * 16;
    int tid = threadIdx.x;
    for (int idx = tid; idx < H1DIM * 16; idx += 128) {
        int aq = idx / H1DIM, k = idx - aq * H1DIM;
        sh[k * 16 + aq] = g_h1[(a0 + aq) * H1DIM + k];
    }
    __syncthreads();

    float acc[16];
    float b = ba2[tid];
    #pragma unroll
    for (int q = 0; q < 16; q++) acc[q] = b;
    #pragma unroll 1
    for (int k0 = 0; k0 < H1DIM; k0 += 8) {
        float wr[8];
        #pragma unroll
        for (int u = 0; u < 8; u++) wr[u] = Wa2[(k0 + u) * H2DIM + tid];
        #pragma unroll
        for (int u = 0; u < 8; u++) {
            float w = wr[u];
            const float4* s4 = reinterpret_cast<const float4*>(sh + (k0 + u) * 16);
            float4 h0 = s4[0], h1 = s4[1], h2 = s4[2], h3 = s4[3];
            acc[ 0] += h0.x * w; acc[ 1] += h0.y * w; acc[ 2] += h0.z * w; acc[ 3] += h0.w * w;
            acc[ 4] += h1.x * w; acc[ 5] += h1.y * w; acc[ 6] += h1.z * w; acc[ 7] += h1.w * w;
            acc[ 8] += h2.x * w; acc[ 9] += h2.y * w; acc[10] += h2.z * w; acc[11] += h2.w * w;
            acc[12] += h3.x * w; acc[13] += h3.y * w; acc[14] += h3.z * w; acc[15] += h3.w * w;
        }
    }
    float w3 = Wa3[tid];
    #pragma unroll
    for (int aq = 0; aq < 16; aq++) she[aq * 128 + tid] = silu_f(acc[aq]) * w3;
    __syncthreads();
    if (tid < 16) {
        float s = ba3[0];
        for (int m = 0; m < 128; m++) s += she[tid * 128 + m];
        g_ebuf[a0 + tid] = s;
    }
}

// ================= Kernel 8: deterministic tree reduction =================
__global__ void k_reduce(float* __restrict__ out)
{
    __shared__ float sr[1024];
    int tid = threadIdx.x;
    sr[tid] = g_ebuf[tid] + g_ebuf[tid + 1024];
    __syncthreads();
    for (int s = 512; s > 0; s >>= 1) {
        if (tid < s) sr[tid] += sr[tid + s];
        __syncthreads();
    }
    if (tid == 0) out[0] = sr[0];
}

// ================= launch =================
extern "C" void kernel_launch(void* const* d_in, const int* in_sizes, int n_in,
                              void* d_out, int out_size)
{
    const float* rij  = (const float*)d_in[0];
    const float* Wr1  = (const float*)d_in[1];
    const float* br1  = (const float*)d_in[2];
    const float* Wr2  = (const float*)d_in[3];
    const float* br2  = (const float*)d_in[4];
    const float* Ws1  = (const float*)d_in[5];
    const float* bs1  = (const float*)d_in[6];
    const float* Ws2  = (const float*)d_in[7];
    const float* bs2  = (const float*)d_in[8];
    const float* Wa1  = (const float*)d_in[9];
    const float* ba1  = (const float*)d_in[10];
    const float* Wa2  = (const float*)d_in[11];
    const float* ba2  = (const float*)d_in[12];
    const float* Wa3  = (const float*)d_in[13];
    const float* ba3  = (const float*)d_in[14];
    const int*   fai  = (const int*)d_in[15];
    const int*   spc  = (const int*)d_in[16];
    float* out = (float*)d_out;

    // Order chosen so the ncu single-kernel capture lands on k_accum this round.
    k_radial<<<NEDGE / 256, 256>>>(rij, Wr1, br1, Wr2, br2);
    k_emb<<<NELEM, 32>>>(Ws1, bs1, Ws2, bs2);
    k_group<<<1, 256>>>(spc);
    k_accum<<<NATOMS, 256>>>(rij, fai);
    k_wtilde<<<dim3(NFEAT, 6), 256>>>(Wa1);
    k_gemm1<<<dim3(NELEM, 2, 2), 128>>>(ba1);
    k_tail<<<NATOMS / 16, 128>>>(Wa2, ba2, Wa3, ba3);
    k_reduce<<<1, 1024>>>(out);
}